// round 5
// baseline (speedup 1.0000x reference)
#include <cuda_runtime.h>

#define NN 50000
#define NE 800000
#define FDIM 128
#define NREL 4
#define BN_EPS 1e-5f

#define TM 128
#define LDA 132
#define NBLK ((NN + TM - 1) / TM)   // 391
#define SMEM_BYTES ((TM * LDA + FDIM * FDIM) * 4)   // 133,120 B
#define NTHR 512

// scratch (device globals; float4-typed for 16B alignment)
__device__ float4 g_h0[(size_t)NREL * NN * FDIM / 4];
__device__ float4 g_h1[(size_t)NREL * NN * FDIM / 4];
__device__ float  g_sum[NREL * FDIM];
__device__ float  g_sumsq[NREL * FDIM];
__device__ float4 g_scale[NREL * FDIM / 4];
__device__ float4 g_shift[NREL * FDIM / 4];
__device__ float4 g_bias[FDIM / 4];

// ---- packed f32x2 helpers (FFMA2 is PTX-only; ptxas never auto-fuses) ----
__device__ __forceinline__ void ffma2(unsigned long long& d,
                                      unsigned long long a,
                                      unsigned long long b) {
    asm("fma.rn.f32x2 %0, %1, %2, %0;" : "+l"(d) : "l"(a), "l"(b));
}
__device__ __forceinline__ unsigned long long bcast2(float x) {
    unsigned long long r;
    asm("mov.b64 %0, {%1, %1};" : "=l"(r) : "f"(x));
    return r;
}
__device__ __forceinline__ float2 unpk2(unsigned long long v) {
    float2 r;
    asm("mov.b64 {%0, %1}, %2;" : "=f"(r.x), "=f"(r.y) : "l"(v));
    return r;
}

// ---------------------------------------------------------------------------
// h0[r][n][:] = x[n][:]
// ---------------------------------------------------------------------------
__global__ void k_init(const float* __restrict__ x) {
    int i = blockIdx.x * blockDim.x + threadIdx.x;
    const int total = NREL * NN * (FDIM / 4);
    if (i >= total) return;
    const int per = NN * (FDIM / 4);
    g_h0[i] = ((const float4*)x)[i % per];
}

__global__ void k_zero_stats() {
    int i = threadIdx.x;
    if (i < NREL * FDIM) { g_sum[i] = 0.f; g_sumsq[i] = 0.f; }
}

// ---------------------------------------------------------------------------
// scatter: h0[rel][dst][:] += x[src][:]  (vector RED, 32 threads per edge)
// ---------------------------------------------------------------------------
__global__ void k_scatter(const float* __restrict__ x,
                          const int* __restrict__ edge_index,
                          const int* __restrict__ edge_type) {
    long long g = (long long)blockIdx.x * blockDim.x + threadIdx.x;
    if (g >= (long long)NE * 32) return;
    int e = (int)(g >> 5);
    int q = (int)(g & 31);
    int src = edge_index[e];
    int dst = edge_index[NE + e];
    int rel = edge_type[e];
    if ((unsigned)src >= NN || (unsigned)dst >= NN || (unsigned)rel >= NREL) return;
    float4 v = ((const float4*)(x + (size_t)src * FDIM))[q];
    float* p = (float*)g_h0 + ((size_t)rel * NN + (size_t)dst) * FDIM + q * 4;
    asm volatile("red.global.add.v4.f32 [%0], {%1, %2, %3, %4};"
                 :: "l"(__cvta_generic_to_global(p)),
                    "f"(v.x), "f"(v.y), "f"(v.z), "f"(v.w)
                 : "memory");
}

// ---------------------------------------------------------------------------
// 128x128x128 FFMA2 tile, 512 threads.
// thread (tx = tid&15, ty = tid>>4 in 0..31): rows ty*4..+3,
// cols {tx*4..+3, 64+tx*4..+3}.  acc[i][p] u64 = 2 packed f32 cols.
// ---------------------------------------------------------------------------
#define KLOOP(As, Bs, acc, tx, ty)                                             \
    _Pragma("unroll 1")                                                        \
    for (int kk = 0; kk < FDIM; kk += 4) {                                     \
        float4 a[4];                                                           \
        _Pragma("unroll")                                                      \
        for (int i = 0; i < 4; i++)                                            \
            a[i] = *(const float4*)((As) + ((ty) * 4 + i) * LDA + kk);         \
        _Pragma("unroll")                                                      \
        for (int u = 0; u < 4; u++) {                                          \
            ulonglong2 b0 = *(const ulonglong2*)((Bs) + (kk + u) * FDIM + (tx) * 4);      \
            ulonglong2 b1 = *(const ulonglong2*)((Bs) + (kk + u) * FDIM + 64 + (tx) * 4); \
            _Pragma("unroll")                                                  \
            for (int i = 0; i < 4; i++) {                                      \
                float av = (u == 0) ? a[i].x : (u == 1) ? a[i].y                \
                          : (u == 2) ? a[i].z : a[i].w;                         \
                unsigned long long aa = bcast2(av);                            \
                ffma2(acc[i][0], aa, b0.x);                                    \
                ffma2(acc[i][1], aa, b0.y);                                    \
                ffma2(acc[i][2], aa, b1.x);                                    \
                ffma2(acc[i][3], aa, b1.y);                                    \
            }                                                                  \
        }                                                                      \
    }

// ---------------------------------------------------------------------------
// GEMM1: h1[r] = h0[r] @ W1[r] + b1[r]; fused BN sum/sumsq
// ---------------------------------------------------------------------------
__global__ void __launch_bounds__(NTHR, 1) k_gemm1(const float* __restrict__ W1,
                                                   const float* __restrict__ b1) {
    extern __shared__ float smem[];
    float* As = smem;                  // [128][LDA]
    float* Bs = smem + TM * LDA;       // [128][128]
    const int r = blockIdx.y;
    const int n0 = blockIdx.x * TM;
    const int tid = threadIdx.x;
    const int tx = tid & 15;
    const int ty = tid >> 4;

    const float* A = (const float*)g_h0 + (size_t)r * NN * FDIM;
    const float4* B4 = (const float4*)(W1 + r * FDIM * FDIM);

#pragma unroll
    for (int i = 0; i < 8; i++)
        ((float4*)Bs)[i * NTHR + tid] = B4[i * NTHR + tid];

#pragma unroll
    for (int i = 0; i < 8; i++) {
        int idx = i * NTHR + tid;
        int row = idx >> 5, c4 = idx & 31;
        float4 v = make_float4(0.f, 0.f, 0.f, 0.f);
        int n = n0 + row;
        if (n < NN) v = ((const float4*)(A + (size_t)n * FDIM))[c4];
        *(float4*)(As + row * LDA + c4 * 4) = v;
    }
    __syncthreads();

    unsigned long long acc[4][4];
#pragma unroll
    for (int i = 0; i < 4; i++)
#pragma unroll
        for (int p = 0; p < 4; p++) acc[i][p] = 0ull;

    KLOOP(As, Bs, acc, tx, ty)

    __syncthreads();   // k-loop tile reads done; smem reused for reduction

    const float* b1p = b1 + r * FDIM;
    float4 bias0 = *(const float4*)(b1p + tx * 4);
    float4 bias1 = *(const float4*)(b1p + 64 + tx * 4);

    float s[8], q[8];
#pragma unroll
    for (int j = 0; j < 8; j++) { s[j] = 0.f; q[j] = 0.f; }

    float* Hout = (float*)g_h1 + (size_t)r * NN * FDIM;
#pragma unroll
    for (int i = 0; i < 4; i++) {
        int n = n0 + ty * 4 + i;
        if (n < NN) {
            float2 p0 = unpk2(acc[i][0]), p1 = unpk2(acc[i][1]);
            float2 p2 = unpk2(acc[i][2]), p3 = unpk2(acc[i][3]);
            float v[8] = {p0.x + bias0.x, p0.y + bias0.y, p1.x + bias0.z, p1.y + bias0.w,
                          p2.x + bias1.x, p2.y + bias1.y, p3.x + bias1.z, p3.y + bias1.w};
#pragma unroll
            for (int j = 0; j < 8; j++) { s[j] += v[j]; q[j] += v[j] * v[j]; }
            float4* o0 = (float4*)(Hout + (size_t)n * FDIM + tx * 4);
            float4* o1 = (float4*)(Hout + (size_t)n * FDIM + 64 + tx * 4);
            *o0 = make_float4(v[0], v[1], v[2], v[3]);
            *o1 = make_float4(v[4], v[5], v[6], v[7]);
        }
    }

    // column reduce over 32 ty-groups, then one atomic per column
    float* redS = As;   // [32][128]
    float* redQ = Bs;   // [32][128]
#pragma unroll
    for (int j = 0; j < 4; j++) {
        redS[ty * FDIM + tx * 4 + j] = s[j];
        redQ[ty * FDIM + tx * 4 + j] = q[j];
        redS[ty * FDIM + 64 + tx * 4 + j] = s[4 + j];
        redQ[ty * FDIM + 64 + tx * 4 + j] = q[4 + j];
    }
#pragma unroll
    for (int off = 16; off > 0; off >>= 1) {
        __syncthreads();
        if (ty < off) {
#pragma unroll
            for (int j = 0; j < 4; j++) {
                int c0 = tx * 4 + j, c1 = 64 + tx * 4 + j;
                redS[ty * FDIM + c0] += redS[(ty + off) * FDIM + c0];
                redQ[ty * FDIM + c0] += redQ[(ty + off) * FDIM + c0];
                redS[ty * FDIM + c1] += redS[(ty + off) * FDIM + c1];
                redQ[ty * FDIM + c1] += redQ[(ty + off) * FDIM + c1];
            }
        }
    }
    __syncthreads();
    if (ty == 0) {
#pragma unroll
        for (int j = 0; j < 4; j++) {
            int c0 = tx * 4 + j, c1 = 64 + tx * 4 + j;
            atomicAdd(&g_sum[r * FDIM + c0], redS[c0]);
            atomicAdd(&g_sumsq[r * FDIM + c0], redQ[c0]);
            atomicAdd(&g_sum[r * FDIM + c1], redS[c1]);
            atomicAdd(&g_sumsq[r * FDIM + c1], redQ[c1]);
        }
    }
}

// ---------------------------------------------------------------------------
// BN scale/shift + folded output biases
// ---------------------------------------------------------------------------
__global__ void k_bn(const float* __restrict__ gamma, const float* __restrict__ beta,
                     const float* __restrict__ b_self, const float* __restrict__ b2) {
    int i = threadIdx.x;
    if (i < NREL * FDIM) {
        const float invN = 1.f / (float)NN;
        float mean = g_sum[i] * invN;
        float var = g_sumsq[i] * invN - mean * mean;
        float sc = gamma[i] * rsqrtf(var + BN_EPS);
        ((float*)g_scale)[i] = sc;
        ((float*)g_shift)[i] = beta[i] - mean * sc;
    }
    if (i < FDIM) {
        float b = b_self[i];
#pragma unroll
        for (int r = 0; r < NREL; r++) b += b2[r * FDIM + i];
        ((float*)g_bias)[i] = b;
    }
}

// ---------------------------------------------------------------------------
// GEMM2 (K=640): out = sum_r relu(bn(h1[r])) @ W2[r] + x @ W_self + g_bias
// ---------------------------------------------------------------------------
__global__ void __launch_bounds__(NTHR, 1) k_gemm2(const float* __restrict__ x,
                                                   const float* __restrict__ W2,
                                                   const float* __restrict__ W_self,
                                                   float* __restrict__ out) {
    extern __shared__ float smem[];
    float* As = smem;
    float* Bs = smem + TM * LDA;
    const int n0 = blockIdx.x * TM;
    const int tid = threadIdx.x;
    const int tx = tid & 15;
    const int ty = tid >> 4;

    unsigned long long acc[4][4];
#pragma unroll
    for (int i = 0; i < 4; i++)
#pragma unroll
        for (int p = 0; p < 4; p++) acc[i][p] = 0ull;

    for (int r = 0; r < NREL + 1; r++) {
        __syncthreads();

        const float4* B4 = (r < NREL) ? (const float4*)(W2 + r * FDIM * FDIM)
                                      : (const float4*)W_self;
#pragma unroll
        for (int i = 0; i < 8; i++)
            ((float4*)Bs)[i * NTHR + tid] = B4[i * NTHR + tid];

        if (r < NREL) {
            const float* H = (const float*)g_h1 + (size_t)r * NN * FDIM;
            const float4* sc4 = g_scale + r * (FDIM / 4);
            const float4* sh4 = g_shift + r * (FDIM / 4);
#pragma unroll
            for (int i = 0; i < 8; i++) {
                int idx = i * NTHR + tid;
                int row = idx >> 5, c4 = idx & 31;
                float4 v = make_float4(0.f, 0.f, 0.f, 0.f);
                int n = n0 + row;
                if (n < NN) {
                    v = ((const float4*)(H + (size_t)n * FDIM))[c4];
                    float4 sc = sc4[c4], sh = sh4[c4];
                    v.x = fmaxf(v.x * sc.x + sh.x, 0.f);
                    v.y = fmaxf(v.y * sc.y + sh.y, 0.f);
                    v.z = fmaxf(v.z * sc.z + sh.z, 0.f);
                    v.w = fmaxf(v.w * sc.w + sh.w, 0.f);
                }
                *(float4*)(As + row * LDA + c4 * 4) = v;
            }
        } else {
#pragma unroll
            for (int i = 0; i < 8; i++) {
                int idx = i * NTHR + tid;
                int row = idx >> 5, c4 = idx & 31;
                float4 v = make_float4(0.f, 0.f, 0.f, 0.f);
                int n = n0 + row;
                if (n < NN) v = ((const float4*)(x + (size_t)n * FDIM))[c4];
                *(float4*)(As + row * LDA + c4 * 4) = v;
            }
        }
        __syncthreads();

        KLOOP(As, Bs, acc, tx, ty)
    }

    float4 bias0 = g_bias[tx];
    float4 bias1 = g_bias[16 + tx];

#pragma unroll
    for (int i = 0; i < 4; i++) {
        int n = n0 + ty * 4 + i;
        if (n < NN) {
            float2 p0 = unpk2(acc[i][0]), p1 = unpk2(acc[i][1]);
            float2 p2 = unpk2(acc[i][2]), p3 = unpk2(acc[i][3]);
            float4* o0 = (float4*)(out + (size_t)n * FDIM + tx * 4);
            float4* o1 = (float4*)(out + (size_t)n * FDIM + 64 + tx * 4);
            *o0 = make_float4(p0.x + bias0.x, p0.y + bias0.y,
                              p1.x + bias0.z, p1.y + bias0.w);
            *o1 = make_float4(p2.x + bias1.x, p2.y + bias1.y,
                              p3.x + bias1.z, p3.y + bias1.w);
        }
    }
}

extern "C" void kernel_launch(void* const* d_in, const int* in_sizes, int n_in,
                              void* d_out, int out_size) {
    const float* x          = (const float*)d_in[0];
    const int*   edge_index = (const int*)d_in[1];   // int32 (JAX x64 disabled)
    const int*   edge_type  = (const int*)d_in[2];
    const float* W_self     = (const float*)d_in[3];
    const float* b_self     = (const float*)d_in[4];
    const float* W1         = (const float*)d_in[5];
    const float* b1         = (const float*)d_in[6];
    const float* gamma      = (const float*)d_in[7];
    const float* beta       = (const float*)d_in[8];
    const float* W2         = (const float*)d_in[9];
    const float* b2         = (const float*)d_in[10];
    float* out = (float*)d_out;

    cudaFuncSetAttribute(k_gemm1, cudaFuncAttributeMaxDynamicSharedMemorySize, SMEM_BYTES);
    cudaFuncSetAttribute(k_gemm2, cudaFuncAttributeMaxDynamicSharedMemorySize, SMEM_BYTES);

    k_init<<<(NREL * NN * (FDIM / 4) + 255) / 256, 256>>>(x);
    k_zero_stats<<<1, 512>>>();
    k_scatter<<<(NE * 32 + 255) / 256, 256>>>(x, edge_index, edge_type);
    dim3 g1(NBLK, NREL);
    k_gemm1<<<g1, NTHR, SMEM_BYTES>>>(W1, b1);
    k_bn<<<1, 512>>>(gamma, beta, b_self, b2);
    k_gemm2<<<NBLK, NTHR, SMEM_BYTES>>>(x, W2, W_self, out);
}

// round 7
// speedup vs baseline: 1.3801x; 1.3801x over previous
#include <cuda_runtime.h>
#include <cuda_bf16.h>
#include <cstdint>

#define NN 50000
#define NE 800000
#define FDIM 128
#define NREL 4
#define BN_EPS 1e-5f
#define TM 128
#define NBLK ((NN + TM - 1) / TM)   // 391
#define NT 256

// bf16 tile stride: 136 elems (272B): 68 words % 32 = 4 -> conflict-free frags
#define STRD 136
#define TILE_B (TM * STRD * 2)      // 34816 B per bf16 tile
#define SM_AH 0
#define SM_AL (SM_AH + TILE_B)
#define SM_BH (SM_AL + TILE_B)
#define SM_BL (SM_BH + TILE_B)
#define SM_TOTAL (SM_BL + TILE_B)   // 139264 B
#define EPI_LD 132                  // fp32 epilogue staging stride (words)

// scratch
__device__ float4 g_h0[(size_t)NREL * NN * FDIM / 4];
__device__ float4 g_h1[(size_t)NREL * NN * FDIM / 4];
__device__ float  g_sum[NREL * FDIM];
__device__ float  g_sumsq[NREL * FDIM];
__device__ float4 g_scale[NREL * FDIM / 4];
__device__ float4 g_shift[NREL * FDIM / 4];
__device__ float4 g_bias[FDIM / 4];
// staged weights: 9 tiles (W1 r0-3, W2 r0-3, W_self), hi/lo, [n][k] bf16
__device__ uint4 g_wst[9][2][2048];

// ---------------------------------------------------------------------------
__device__ __forceinline__ void mma16816(float* c, const unsigned* a,
                                         unsigned b0, unsigned b1) {
    asm volatile(
        "mma.sync.aligned.m16n8k16.row.col.f32.bf16.bf16.f32 "
        "{%0,%1,%2,%3}, {%4,%5,%6,%7}, {%8,%9}, {%0,%1,%2,%3};"
        : "+f"(c[0]), "+f"(c[1]), "+f"(c[2]), "+f"(c[3])
        : "r"(a[0]), "r"(a[1]), "r"(a[2]), "r"(a[3]), "r"(b0), "r"(b1));
}

// split fp32x4 (cols c0..c0+3 of row) into bf16 hi/lo, store to Ah/Al
__device__ __forceinline__ void split_store(char* smem, int row, int c0, float4 v) {
    unsigned off = (unsigned)(row * STRD + c0) * 2;
    __nv_bfloat16 h0 = __float2bfloat16_rn(v.x), h1 = __float2bfloat16_rn(v.y);
    __nv_bfloat16 h2 = __float2bfloat16_rn(v.z), h3 = __float2bfloat16_rn(v.w);
    __nv_bfloat16 g0 = __float2bfloat16_rn(v.x - __bfloat162float(h0));
    __nv_bfloat16 g1 = __float2bfloat16_rn(v.y - __bfloat162float(h1));
    __nv_bfloat16 g2 = __float2bfloat16_rn(v.z - __bfloat162float(h2));
    __nv_bfloat16 g3 = __float2bfloat16_rn(v.w - __bfloat162float(h3));
    uint2 uh, ul;
    uh.x = (unsigned)__bfloat16_as_ushort(h0) | ((unsigned)__bfloat16_as_ushort(h1) << 16);
    uh.y = (unsigned)__bfloat16_as_ushort(h2) | ((unsigned)__bfloat16_as_ushort(h3) << 16);
    ul.x = (unsigned)__bfloat16_as_ushort(g0) | ((unsigned)__bfloat16_as_ushort(g1) << 16);
    ul.y = (unsigned)__bfloat16_as_ushort(g2) | ((unsigned)__bfloat16_as_ushort(g3) << 16);
    *(uint2*)(smem + SM_AH + off) = uh;
    *(uint2*)(smem + SM_AL + off) = ul;
}

// 3-pass bf16-split 128x128x128 MMA tile; accumulates into acc
__device__ __forceinline__ void mma_tile(const char* smem, float acc[2][8][4],
                                         int wm, int wn, int g, int tg) {
#pragma unroll 1
    for (int pass = 0; pass < 3; pass++) {
        const char* Asrc = smem + (pass == 2 ? SM_AL : SM_AH);
        const char* Bsrc = smem + (pass == 1 ? SM_BL : SM_BH);
#pragma unroll 1
        for (int ks = 0; ks < 8; ks++) {
            const int k0 = ks * 16;
            unsigned a[2][4];
#pragma unroll
            for (int mf = 0; mf < 2; mf++) {
                const char* ab = Asrc +
                    (unsigned)((wm * 32 + mf * 16 + g) * STRD + k0 + tg * 2) * 2;
                a[mf][0] = *(const unsigned*)ab;
                a[mf][1] = *(const unsigned*)(ab + 8 * STRD * 2);
                a[mf][2] = *(const unsigned*)(ab + 16);
                a[mf][3] = *(const unsigned*)(ab + 8 * STRD * 2 + 16);
            }
#pragma unroll
            for (int nf = 0; nf < 8; nf++) {
                const char* bb = Bsrc +
                    (unsigned)((wn * 64 + nf * 8 + g) * STRD + k0 + tg * 2) * 2;
                unsigned b0 = *(const unsigned*)bb;
                unsigned b1 = *(const unsigned*)(bb + 16);
                mma16816(acc[0][nf], a[0], b0, b1);
                mma16816(acc[1][nf], a[1], b0, b1);
            }
        }
    }
}

// write accumulators to fp32 staging E[128][EPI_LD]
__device__ __forceinline__ void epi_store(float* E, float acc[2][8][4],
                                          int wm, int wn, int g, int tg) {
#pragma unroll
    for (int mf = 0; mf < 2; mf++)
#pragma unroll
        for (int nf = 0; nf < 8; nf++) {
            int row = wm * 32 + mf * 16 + g;
            int col = wn * 64 + nf * 8 + tg * 2;
            *(float2*)(E + row * EPI_LD + col) =
                make_float2(acc[mf][nf][0], acc[mf][nf][1]);
            *(float2*)(E + (row + 8) * EPI_LD + col) =
                make_float2(acc[mf][nf][2], acc[mf][nf][3]);
        }
}

// ---------------------------------------------------------------------------
__global__ void k_init(const float* __restrict__ x) {
    int i = blockIdx.x * blockDim.x + threadIdx.x;
    const int total = NREL * NN * (FDIM / 4);
    if (i >= total) return;
    const int per = NN * (FDIM / 4);
    g_h0[i] = ((const float4*)x)[i % per];
}

__global__ void k_zero_stats() {
    int i = threadIdx.x;
    if (i < NREL * FDIM) { g_sum[i] = 0.f; g_sumsq[i] = 0.f; }
}

__global__ void k_scatter(const float* __restrict__ x,
                          const int* __restrict__ edge_index,
                          const int* __restrict__ edge_type) {
    long long g = (long long)blockIdx.x * blockDim.x + threadIdx.x;
    if (g >= (long long)NE * 32) return;
    int e = (int)(g >> 5);
    int q = (int)(g & 31);
    int src = edge_index[e];
    int dst = edge_index[NE + e];
    int rel = edge_type[e];
    if ((unsigned)src >= NN || (unsigned)dst >= NN || (unsigned)rel >= NREL) return;
    float4 v = ((const float4*)(x + (size_t)src * FDIM))[q];
    float* p = (float*)g_h0 + ((size_t)rel * NN + (size_t)dst) * FDIM + q * 4;
    asm volatile("red.global.add.v4.f32 [%0], {%1, %2, %3, %4};"
                 :: "l"(__cvta_generic_to_global(p)),
                    "f"(v.x), "f"(v.y), "f"(v.z), "f"(v.w)
                 : "memory");
}

// stage weights: split bf16 hi/lo, transpose to [n][k]
__global__ void k_prepw(const float* __restrict__ W1,
                        const float* __restrict__ W2,
                        const float* __restrict__ W_self) {
    int t = blockIdx.x;   // 0..8
    const float* src = (t < 4) ? W1 + t * FDIM * FDIM
                     : (t < 8) ? W2 + (t - 4) * FDIM * FDIM
                               : W_self;
    unsigned short* dh = (unsigned short*)g_wst[t][0];
    unsigned short* dl = (unsigned short*)g_wst[t][1];
    for (int idx = threadIdx.x; idx < FDIM * FDIM; idx += blockDim.x) {
        int k = idx >> 7;     // source row (K)
        int n = idx & 127;    // source col (N) -> dest row
        float w = src[idx];
        __nv_bfloat16 hi = __float2bfloat16_rn(w);
        __nv_bfloat16 lo = __float2bfloat16_rn(w - __bfloat162float(hi));
        dh[n * FDIM + k] = __bfloat16_as_ushort(hi);
        dl[n * FDIM + k] = __bfloat16_as_ushort(lo);
    }
}

__global__ void k_bn(const float* __restrict__ gamma, const float* __restrict__ beta,
                     const float* __restrict__ b_self, const float* __restrict__ b2) {
    int i = threadIdx.x;
    if (i < NREL * FDIM) {
        const float invN = 1.f / (float)NN;
        float mean = g_sum[i] * invN;
        float var = g_sumsq[i] * invN - mean * mean;
        float sc = gamma[i] * rsqrtf(var + BN_EPS);
        ((float*)g_scale)[i] = sc;
        ((float*)g_shift)[i] = beta[i] - mean * sc;
    }
    if (i < FDIM) {
        float b = b_self[i];
#pragma unroll
        for (int r = 0; r < NREL; r++) b += b2[r * FDIM + i];
        ((float*)g_bias)[i] = b;
    }
}

// ---------------------------------------------------------------------------
// GEMM1 (mma.sync bf16-split): h1[r] = h0[r] @ W1[r] + b1[r]; fused BN stats
// ---------------------------------------------------------------------------
__global__ void __launch_bounds__(NT, 1) k_gemm1(const float* __restrict__ b1) {
    extern __shared__ char smem[];
    const int tid = threadIdx.x;
    const int wid = tid >> 5, lid = tid & 31;
    const int wm = wid & 3, wn = wid >> 2;
    const int g = lid >> 2, tg = lid & 3;
    const int r = blockIdx.y;
    const int n0 = blockIdx.x * TM;
    const int valid = min(NN - n0, TM);

    // stage A: fp32 h0 -> bf16 hi/lo
    const float* A = (const float*)g_h0 + (size_t)r * NN * FDIM;
#pragma unroll
    for (int i = 0; i < 16; i++) {
        int idx = i * NT + tid;
        int row = idx >> 5, c4 = idx & 31;
        float4 v = make_float4(0.f, 0.f, 0.f, 0.f);
        if (row < valid) v = ((const float4*)(A + (size_t)(n0 + row) * FDIM))[c4];
        split_store(smem, row, c4 * 4, v);
    }
    // stage B: copy staged weights into padded smem
#pragma unroll
    for (int i = 0; i < 8; i++) {
        int idx = i * NT + tid;
        int n = idx >> 4, c = idx & 15;
        *(uint4*)(smem + SM_BH + n * STRD * 2 + c * 16) = g_wst[r][0][idx];
        *(uint4*)(smem + SM_BL + n * STRD * 2 + c * 16) = g_wst[r][1][idx];
    }
    __syncthreads();

    float acc[2][8][4];
#pragma unroll
    for (int mf = 0; mf < 2; mf++)
#pragma unroll
        for (int nf = 0; nf < 8; nf++)
#pragma unroll
            for (int j = 0; j < 4; j++) acc[mf][nf][j] = 0.f;

    mma_tile(smem, acc, wm, wn, g, tg);
    __syncthreads();   // smem reads done; reuse for epilogue

    float* E = (float*)smem;   // [128][EPI_LD] fp32, 67584 B (over Ah/Al)
    epi_store(E, acc, wm, wn, g, tg);
    __syncthreads();

    // coalesced h1 write + bias + BN partial stats
    const int c4 = tid & 31, rg = tid >> 5;
    float4 bias = *(const float4*)(b1 + r * FDIM + c4 * 4);
    float s4[4] = {0, 0, 0, 0}, q4[4] = {0, 0, 0, 0};
    float* Hout = (float*)g_h1 + (size_t)r * NN * FDIM;
#pragma unroll
    for (int i = 0; i < 16; i++) {
        int row = i * 8 + rg;
        if (row < valid) {
            float4 v = *(float4*)(E + row * EPI_LD + c4 * 4);
            v.x += bias.x; v.y += bias.y; v.z += bias.z; v.w += bias.w;
            s4[0] += v.x; q4[0] += v.x * v.x;
            s4[1] += v.y; q4[1] += v.y * v.y;
            s4[2] += v.z; q4[2] += v.z * v.z;
            s4[3] += v.w; q4[3] += v.w * v.w;
            *(float4*)(Hout + (size_t)(n0 + row) * FDIM + c4 * 4) = v;
        }
    }
    // stats reduce: partials [8][128] in SM_BH region (disjoint from E)
    float* redS = (float*)(smem + SM_BH);
    float* redQ = redS + 8 * FDIM;
#pragma unroll
    for (int j = 0; j < 4; j++) {
        redS[rg * FDIM + c4 * 4 + j] = s4[j];
        redQ[rg * FDIM + c4 * 4 + j] = q4[j];
    }
    __syncthreads();
    if (tid < FDIM) {
        float S = 0.f, Q = 0.f;
#pragma unroll
        for (int p = 0; p < 8; p++) { S += redS[p * FDIM + tid]; Q += redQ[p * FDIM + tid]; }
        atomicAdd(&g_sum[r * FDIM + tid], S);
        atomicAdd(&g_sumsq[r * FDIM + tid], Q);
    }
}

// ---------------------------------------------------------------------------
// GEMM2 (mma.sync, K=640): out = sum_r relu(bn(h1[r])) @ W2[r] + x @ W_self + bias
// ---------------------------------------------------------------------------
__global__ void __launch_bounds__(NT, 1) k_gemm2(const float* __restrict__ x,
                                                 float* __restrict__ out) {
    extern __shared__ char smem[];
    const int tid = threadIdx.x;
    const int wid = tid >> 5, lid = tid & 31;
    const int wm = wid & 3, wn = wid >> 2;
    const int g = lid >> 2, tg = lid & 3;
    const int n0 = blockIdx.x * TM;
    const int valid = min(NN - n0, TM);

    float acc[2][8][4];
#pragma unroll
    for (int mf = 0; mf < 2; mf++)
#pragma unroll
        for (int nf = 0; nf < 8; nf++)
#pragma unroll
            for (int j = 0; j < 4; j++) acc[mf][nf][j] = 0.f;

    for (int r = 0; r < NREL + 1; r++) {
        __syncthreads();   // previous stage's smem reads done

        if (r < NREL) {
            const float* H = (const float*)g_h1 + (size_t)r * NN * FDIM;
#pragma unroll
            for (int i = 0; i < 16; i++) {
                int idx = i * NT + tid;
                int row = idx >> 5, c4 = idx & 31;
                float4 v = make_float4(0.f, 0.f, 0.f, 0.f);
                if (row < valid) {
                    v = ((const float4*)(H + (size_t)(n0 + row) * FDIM))[c4];
                    float4 sc = g_scale[r * (FDIM / 4) + c4];
                    float4 sh = g_shift[r * (FDIM / 4) + c4];
                    v.x = fmaxf(v.x * sc.x + sh.x, 0.f);
                    v.y = fmaxf(v.y * sc.y + sh.y, 0.f);
                    v.z = fmaxf(v.z * sc.z + sh.z, 0.f);
                    v.w = fmaxf(v.w * sc.w + sh.w, 0.f);
                }
                split_store(smem, row, c4 * 4, v);
            }
        } else {
#pragma unroll
            for (int i = 0; i < 16; i++) {
                int idx = i * NT + tid;
                int row = idx >> 5, c4 = idx & 31;
                float4 v = make_float4(0.f, 0.f, 0.f, 0.f);
                if (row < valid) v = ((const float4*)(x + (size_t)(n0 + row) * FDIM))[c4];
                split_store(smem, row, c4 * 4, v);
            }
        }
        {
            int t = (r < NREL) ? 4 + r : 8;
#pragma unroll
            for (int i = 0; i < 8; i++) {
                int idx = i * NT + tid;
                int n = idx >> 4, c = idx & 15;
                *(uint4*)(smem + SM_BH + n * STRD * 2 + c * 16) = g_wst[t][0][idx];
                *(uint4*)(smem + SM_BL + n * STRD * 2 + c * 16) = g_wst[t][1][idx];
            }
        }
        __syncthreads();

        mma_tile(smem, acc, wm, wn, g, tg);
    }
    __syncthreads();

    float* E = (float*)smem;
    epi_store(E, acc, wm, wn, g, tg);
    __syncthreads();

    const int c4 = tid & 31, rg = tid >> 5;
    float4 bias = g_bias[c4];
#pragma unroll
    for (int i = 0; i < 16; i++) {
        int row = i * 8 + rg;
        if (row < valid) {
            float4 v = *(float4*)(E + row * EPI_LD + c4 * 4);
            v.x += bias.x; v.y += bias.y; v.z += bias.z; v.w += bias.w;
            *(float4*)(out + (size_t)(n0 + row) * FDIM + c4 * 4) = v;
        }
    }
}

extern "C" void kernel_launch(void* const* d_in, const int* in_sizes, int n_in,
                              void* d_out, int out_size) {
    const float* x          = (const float*)d_in[0];
    const int*   edge_index = (const int*)d_in[1];   // int32 (JAX x64 disabled)
    const int*   edge_type  = (const int*)d_in[2];
    const float* W_self     = (const float*)d_in[3];
    const float* b_self     = (const float*)d_in[4];
    const float* W1         = (const float*)d_in[5];
    const float* b1         = (const float*)d_in[6];
    const float* gamma      = (const float*)d_in[7];
    const float* beta       = (const float*)d_in[8];
    const float* W2         = (const float*)d_in[9];
    const float* b2         = (const float*)d_in[10];
    float* out = (float*)d_out;

    cudaFuncSetAttribute(k_gemm1, cudaFuncAttributeMaxDynamicSharedMemorySize, SM_TOTAL);
    cudaFuncSetAttribute(k_gemm2, cudaFuncAttributeMaxDynamicSharedMemorySize, SM_TOTAL);

    k_init<<<(NREL * NN * (FDIM / 4) + 255) / 256, 256>>>(x);
    k_zero_stats<<<1, 512>>>();
    k_prepw<<<9, 256>>>(W1, W2, W_self);
    k_scatter<<<(NE * 32 + 255) / 256, 256>>>(x, edge_index, edge_type);
    dim3 g1(NBLK, NREL);
    k_gemm1<<<g1, NT, SM_TOTAL>>>(b1);
    k_bn<<<1, 512>>>(gamma, beta, b_self, b2);
    k_gemm2<<<NBLK, NT, SM_TOTAL>>>(x, out);
}

// round 8
// speedup vs baseline: 1.4561x; 1.0551x over previous
#include <cuda_runtime.h>
#include <cuda_bf16.h>
#include <cstdint>

#define NN 50000
#define NE 800000
#define FDIM 128
#define NREL 4
#define BN_EPS 1e-5f
#define TM 128
#define NBLK ((NN + TM - 1) / TM)   // 391
#define NT 256

// bf16 tile stride: 136 elems (272B) -> 2-way-max LDS conflicts, 8B aligned
#define STRD 136
#define TILE_B (TM * STRD * 2)      // 34816 B per bf16 tile
// 3-buffer scheme: T0=Ah, T1=Al (later Bl), T2=Bh
#define SM_AH 0
#define SM_AL TILE_B
#define SM_BH (2 * TILE_B)
#define SM_TOTAL (3 * TILE_B)       // 104448 B -> 2 blocks/SM
#define EPI_LD 132                  // fp32 epilogue staging stride (words)

// scratch
__device__ float4 g_h0[(size_t)NREL * NN * FDIM / 4];
__device__ float4 g_h1[(size_t)NREL * NN * FDIM / 4];
__device__ float  g_sum[NREL * FDIM];
__device__ float  g_sumsq[NREL * FDIM];
__device__ float4 g_scale[NREL * FDIM / 4];
__device__ float4 g_shift[NREL * FDIM / 4];
__device__ float4 g_bias[FDIM / 4];
// staged weights: 9 tiles (W1 r0-3, W2 r0-3, W_self), hi/lo, [n][k] bf16
__device__ uint4 g_wst[9][2][2048];

// ---------------------------------------------------------------------------
__device__ __forceinline__ unsigned smem_u32(const void* p) {
    unsigned a;
    asm("{ .reg .u64 t; cvta.to.shared.u64 t, %1; cvt.u32.u64 %0, t; }"
        : "=r"(a) : "l"(p));
    return a;
}
__device__ __forceinline__ void cpa16(unsigned dst, const void* src) {
    asm volatile("cp.async.cg.shared.global [%0], [%1], 16;"
                 :: "r"(dst), "l"(src) : "memory");
}
#define CPA_COMMIT() asm volatile("cp.async.commit_group;" ::: "memory")
#define CPA_WAIT0()  asm volatile("cp.async.wait_group 0;" ::: "memory")

__device__ __forceinline__ void mma16816(float* c, const unsigned* a,
                                         unsigned b0, unsigned b1) {
    asm volatile(
        "mma.sync.aligned.m16n8k16.row.col.f32.bf16.bf16.f32 "
        "{%0,%1,%2,%3}, {%4,%5,%6,%7}, {%8,%9}, {%0,%1,%2,%3};"
        : "+f"(c[0]), "+f"(c[1]), "+f"(c[2]), "+f"(c[3])
        : "r"(a[0]), "r"(a[1]), "r"(a[2]), "r"(a[3]), "r"(b0), "r"(b1));
}

// split fp32x4 (cols c0..c0+3 of row) into bf16 hi/lo, store to Ah/Al
__device__ __forceinline__ void split_store(char* smem, int row, int c0, float4 v) {
    unsigned off = (unsigned)(row * STRD + c0) * 2;
    __nv_bfloat16 h0 = __float2bfloat16_rn(v.x), h1 = __float2bfloat16_rn(v.y);
    __nv_bfloat16 h2 = __float2bfloat16_rn(v.z), h3 = __float2bfloat16_rn(v.w);
    __nv_bfloat16 g0 = __float2bfloat16_rn(v.x - __bfloat162float(h0));
    __nv_bfloat16 g1 = __float2bfloat16_rn(v.y - __bfloat162float(h1));
    __nv_bfloat16 g2 = __float2bfloat16_rn(v.z - __bfloat162float(h2));
    __nv_bfloat16 g3 = __float2bfloat16_rn(v.w - __bfloat162float(h3));
    uint2 uh, ul;
    uh.x = (unsigned)__bfloat16_as_ushort(h0) | ((unsigned)__bfloat16_as_ushort(h1) << 16);
    uh.y = (unsigned)__bfloat16_as_ushort(h2) | ((unsigned)__bfloat16_as_ushort(h3) << 16);
    ul.x = (unsigned)__bfloat16_as_ushort(g0) | ((unsigned)__bfloat16_as_ushort(g1) << 16);
    ul.y = (unsigned)__bfloat16_as_ushort(g2) | ((unsigned)__bfloat16_as_ushort(g3) << 16);
    *(uint2*)(smem + SM_AH + off) = uh;
    *(uint2*)(smem + SM_AL + off) = ul;
}

// one 128x128x128 pass: acc += A(bf16 tile at Asrc) @ B(bf16 tile at Bsrc)^T
__device__ __forceinline__ void mma_pass(const char* Asrc, const char* Bsrc,
                                         float acc[2][8][4],
                                         int wm, int wn, int g, int tg) {
#pragma unroll 1
    for (int ks = 0; ks < 8; ks++) {
        const int k0 = ks * 16;
        unsigned a[2][4];
#pragma unroll
        for (int mf = 0; mf < 2; mf++) {
            const char* ab = Asrc +
                (unsigned)((wm * 32 + mf * 16 + g) * STRD + k0 + tg * 2) * 2;
            a[mf][0] = *(const unsigned*)ab;
            a[mf][1] = *(const unsigned*)(ab + 8 * STRD * 2);
            a[mf][2] = *(const unsigned*)(ab + 16);
            a[mf][3] = *(const unsigned*)(ab + 8 * STRD * 2 + 16);
        }
#pragma unroll
        for (int nf = 0; nf < 8; nf++) {
            const char* bb = Bsrc +
                (unsigned)((wn * 64 + nf * 8 + g) * STRD + k0 + tg * 2) * 2;
            unsigned b0 = *(const unsigned*)bb;
            unsigned b1 = *(const unsigned*)(bb + 16);
            mma16816(acc[0][nf], a[0], b0, b1);
            mma16816(acc[1][nf], a[1], b0, b1);
        }
    }
}

// async copy of one staged 128x128 bf16 weight tile into padded smem
__device__ __forceinline__ void copy_b(unsigned sb_dst, const uint4* src, int tid) {
#pragma unroll
    for (int i = 0; i < 8; i++) {
        int idx = i * NT + tid;
        int n = idx >> 4, c = idx & 15;
        cpa16(sb_dst + n * STRD * 2 + c * 16, src + idx);
    }
}

// write accumulators to fp32 staging E[128][EPI_LD]
__device__ __forceinline__ void epi_store(float* E, float acc[2][8][4],
                                          int wm, int wn, int g, int tg) {
#pragma unroll
    for (int mf = 0; mf < 2; mf++)
#pragma unroll
        for (int nf = 0; nf < 8; nf++) {
            int row = wm * 32 + mf * 16 + g;
            int col = wn * 64 + nf * 8 + tg * 2;
            *(float2*)(E + row * EPI_LD + col) =
                make_float2(acc[mf][nf][0], acc[mf][nf][1]);
            *(float2*)(E + (row + 8) * EPI_LD + col) =
                make_float2(acc[mf][nf][2], acc[mf][nf][3]);
        }
}

// ---------------------------------------------------------------------------
__global__ void k_init(const float* __restrict__ x) {
    int i = blockIdx.x * blockDim.x + threadIdx.x;
    const int total = NREL * NN * (FDIM / 4);
    if (i >= total) return;
    const int per = NN * (FDIM / 4);
    g_h0[i] = ((const float4*)x)[i % per];
}

__global__ void k_zero_stats() {
    int i = threadIdx.x;
    if (i < NREL * FDIM) { g_sum[i] = 0.f; g_sumsq[i] = 0.f; }
}

__global__ void k_scatter(const float* __restrict__ x,
                          const int* __restrict__ edge_index,
                          const int* __restrict__ edge_type) {
    long long g = (long long)blockIdx.x * blockDim.x + threadIdx.x;
    if (g >= (long long)NE * 32) return;
    int e = (int)(g >> 5);
    int q = (int)(g & 31);
    int src = edge_index[e];
    int dst = edge_index[NE + e];
    int rel = edge_type[e];
    if ((unsigned)src >= NN || (unsigned)dst >= NN || (unsigned)rel >= NREL) return;
    float4 v = ((const float4*)(x + (size_t)src * FDIM))[q];
    float* p = (float*)g_h0 + ((size_t)rel * NN + (size_t)dst) * FDIM + q * 4;
    asm volatile("red.global.add.v4.f32 [%0], {%1, %2, %3, %4};"
                 :: "l"(__cvta_generic_to_global(p)),
                    "f"(v.x), "f"(v.y), "f"(v.z), "f"(v.w)
                 : "memory");
}

// stage weights: split bf16 hi/lo, transpose to [n][k]
__global__ void k_prepw(const float* __restrict__ W1,
                        const float* __restrict__ W2,
                        const float* __restrict__ W_self) {
    int t = blockIdx.x;   // 0..8
    const float* src = (t < 4) ? W1 + t * FDIM * FDIM
                     : (t < 8) ? W2 + (t - 4) * FDIM * FDIM
                               : W_self;
    unsigned short* dh = (unsigned short*)g_wst[t][0];
    unsigned short* dl = (unsigned short*)g_wst[t][1];
    for (int idx = threadIdx.x; idx < FDIM * FDIM; idx += blockDim.x) {
        int k = idx >> 7;     // source row (K)
        int n = idx & 127;    // source col (N) -> dest row
        float w = src[idx];
        __nv_bfloat16 hi = __float2bfloat16_rn(w);
        __nv_bfloat16 lo = __float2bfloat16_rn(w - __bfloat162float(hi));
        dh[n * FDIM + k] = __bfloat16_as_ushort(hi);
        dl[n * FDIM + k] = __bfloat16_as_ushort(lo);
    }
}

__global__ void k_bn(const float* __restrict__ gamma, const float* __restrict__ beta,
                     const float* __restrict__ b_self, const float* __restrict__ b2) {
    int i = threadIdx.x;
    if (i < NREL * FDIM) {
        const float invN = 1.f / (float)NN;
        float mean = g_sum[i] * invN;
        float var = g_sumsq[i] * invN - mean * mean;
        float sc = gamma[i] * rsqrtf(var + BN_EPS);
        ((float*)g_scale)[i] = sc;
        ((float*)g_shift)[i] = beta[i] - mean * sc;
    }
    if (i < FDIM) {
        float b = b_self[i];
#pragma unroll
        for (int r = 0; r < NREL; r++) b += b2[r * FDIM + i];
        ((float*)g_bias)[i] = b;
    }
}

// ---------------------------------------------------------------------------
// GEMM1 (mma.sync bf16-split, 3-buffer): h1[r] = h0[r] @ W1[r] + b1[r]
// pass order: Ah*Bh, Al*Bh, [Bl over Al] Ah*Bl  -> 3 tiles live -> 2 blk/SM
// ---------------------------------------------------------------------------
__global__ void __launch_bounds__(NT, 2) k_gemm1(const float* __restrict__ b1) {
    extern __shared__ char smem[];
    const unsigned sb = smem_u32(smem);
    const int tid = threadIdx.x;
    const int wid = tid >> 5, lid = tid & 31;
    const int wm = wid & 3, wn = wid >> 2;
    const int g = lid >> 2, tg = lid & 3;
    const int r = blockIdx.y;
    const int n0 = blockIdx.x * TM;
    const int valid = min(NN - n0, TM);

    // B-hi copy in flight while we convert A
    copy_b(sb + SM_BH, g_wst[r][0], tid);
    CPA_COMMIT();

    const float* A = (const float*)g_h0 + (size_t)r * NN * FDIM;
#pragma unroll
    for (int i = 0; i < 16; i++) {
        int idx = i * NT + tid;
        int row = idx >> 5, c4 = idx & 31;
        float4 v = make_float4(0.f, 0.f, 0.f, 0.f);
        if (row < valid) v = ((const float4*)(A + (size_t)(n0 + row) * FDIM))[c4];
        split_store(smem, row, c4 * 4, v);
    }
    CPA_WAIT0();
    __syncthreads();

    float acc[2][8][4];
#pragma unroll
    for (int mf = 0; mf < 2; mf++)
#pragma unroll
        for (int nf = 0; nf < 8; nf++)
#pragma unroll
            for (int j = 0; j < 4; j++) acc[mf][nf][j] = 0.f;

    mma_pass(smem + SM_AH, smem + SM_BH, acc, wm, wn, g, tg);
    mma_pass(smem + SM_AL, smem + SM_BH, acc, wm, wn, g, tg);
    __syncthreads();                 // Al reads done -> reuse T1 for Bl
    copy_b(sb + SM_AL, g_wst[r][1], tid);
    CPA_COMMIT();
    CPA_WAIT0();
    __syncthreads();
    mma_pass(smem + SM_AH, smem + SM_AL, acc, wm, wn, g, tg);
    __syncthreads();                 // tile reads done; reuse smem

    float* E = (float*)smem;         // [128][EPI_LD] fp32 (67584 B, over T0/T1)
    epi_store(E, acc, wm, wn, g, tg);
    __syncthreads();

    const int c4 = tid & 31, rg = tid >> 5;
    float4 bias = *(const float4*)(b1 + r * FDIM + c4 * 4);
    float s4[4] = {0, 0, 0, 0}, q4[4] = {0, 0, 0, 0};
    float* Hout = (float*)g_h1 + (size_t)r * NN * FDIM;
#pragma unroll
    for (int i = 0; i < 16; i++) {
        int row = i * 8 + rg;
        if (row < valid) {
            float4 v = *(float4*)(E + row * EPI_LD + c4 * 4);
            v.x += bias.x; v.y += bias.y; v.z += bias.z; v.w += bias.w;
            s4[0] += v.x; q4[0] += v.x * v.x;
            s4[1] += v.y; q4[1] += v.y * v.y;
            s4[2] += v.z; q4[2] += v.z * v.z;
            s4[3] += v.w; q4[3] += v.w * v.w;
            *(float4*)(Hout + (size_t)(n0 + row) * FDIM + c4 * 4) = v;
        }
    }
    // stats reduce: partials [8][128] in T2 region (disjoint from E)
    float* redS = (float*)(smem + SM_BH);
    float* redQ = redS + 8 * FDIM;
#pragma unroll
    for (int j = 0; j < 4; j++) {
        redS[rg * FDIM + c4 * 4 + j] = s4[j];
        redQ[rg * FDIM + c4 * 4 + j] = q4[j];
    }
    __syncthreads();
    if (tid < FDIM) {
        float S = 0.f, Q = 0.f;
#pragma unroll
        for (int p = 0; p < 8; p++) { S += redS[p * FDIM + tid]; Q += redQ[p * FDIM + tid]; }
        atomicAdd(&g_sum[r * FDIM + tid], S);
        atomicAdd(&g_sumsq[r * FDIM + tid], Q);
    }
}

// ---------------------------------------------------------------------------
// GEMM2 (mma.sync, K=640, 3-buffer): out = sum_r relu(bn(h1[r])) @ W2[r]
//                                          + x @ W_self + bias
// ---------------------------------------------------------------------------
__global__ void __launch_bounds__(NT, 2) k_gemm2(const float* __restrict__ x,
                                                 float* __restrict__ out) {
    extern __shared__ char smem[];
    const unsigned sb = smem_u32(smem);
    const int tid = threadIdx.x;
    const int wid = tid >> 5, lid = tid & 31;
    const int wm = wid & 3, wn = wid >> 2;
    const int g = lid >> 2, tg = lid & 3;
    const int n0 = blockIdx.x * TM;
    const int valid = min(NN - n0, TM);

    float acc[2][8][4];
#pragma unroll
    for (int mf = 0; mf < 2; mf++)
#pragma unroll
        for (int nf = 0; nf < 8; nf++)
#pragma unroll
            for (int j = 0; j < 4; j++) acc[mf][nf][j] = 0.f;

    for (int r = 0; r < NREL + 1; r++) {
        __syncthreads();   // prior stage's tile reads complete
        const int t = (r < NREL) ? 4 + r : 8;

        copy_b(sb + SM_BH, g_wst[t][0], tid);
        CPA_COMMIT();

        if (r < NREL) {
            const float* H = (const float*)g_h1 + (size_t)r * NN * FDIM;
#pragma unroll
            for (int i = 0; i < 16; i++) {
                int idx = i * NT + tid;
                int row = idx >> 5, c4 = idx & 31;
                float4 v = make_float4(0.f, 0.f, 0.f, 0.f);
                if (row < valid) {
                    v = ((const float4*)(H + (size_t)(n0 + row) * FDIM))[c4];
                    float4 sc = g_scale[r * (FDIM / 4) + c4];
                    float4 sh = g_shift[r * (FDIM / 4) + c4];
                    v.x = fmaxf(v.x * sc.x + sh.x, 0.f);
                    v.y = fmaxf(v.y * sc.y + sh.y, 0.f);
                    v.z = fmaxf(v.z * sc.z + sh.z, 0.f);
                    v.w = fmaxf(v.w * sc.w + sh.w, 0.f);
                }
                split_store(smem, row, c4 * 4, v);
            }
        } else {
#pragma unroll
            for (int i = 0; i < 16; i++) {
                int idx = i * NT + tid;
                int row = idx >> 5, c4 = idx & 31;
                float4 v = make_float4(0.f, 0.f, 0.f, 0.f);
                if (row < valid) v = ((const float4*)(x + (size_t)(n0 + row) * FDIM))[c4];
                split_store(smem, row, c4 * 4, v);
            }
        }
        CPA_WAIT0();
        __syncthreads();

        mma_pass(smem + SM_AH, smem + SM_BH, acc, wm, wn, g, tg);
        mma_pass(smem + SM_AL, smem + SM_BH, acc, wm, wn, g, tg);
        __syncthreads();             // Al reads done -> T1 <- Bl
        copy_b(sb + SM_AL, g_wst[t][1], tid);
        CPA_COMMIT();
        CPA_WAIT0();
        __syncthreads();
        mma_pass(smem + SM_AH, smem + SM_AL, acc, wm, wn, g, tg);
    }
    __syncthreads();

    float* E = (float*)smem;
    epi_store(E, acc, wm, wn, g, tg);
    __syncthreads();

    const int c4 = tid & 31, rg = tid >> 5;
    float4 bias = g_bias[c4];
#pragma unroll
    for (int i = 0; i < 16; i++) {
        int row = i * 8 + rg;
        if (row < valid) {
            float4 v = *(float4*)(E + row * EPI_LD + c4 * 4);
            v.x += bias.x; v.y += bias.y; v.z += bias.z; v.w += bias.w;
            *(float4*)(out + (size_t)(n0 + row) * FDIM + c4 * 4) = v;
        }
    }
}

extern "C" void kernel_launch(void* const* d_in, const int* in_sizes, int n_in,
                              void* d_out, int out_size) {
    const float* x          = (const float*)d_in[0];
    const int*   edge_index = (const int*)d_in[1];   // int32 (JAX x64 disabled)
    const int*   edge_type  = (const int*)d_in[2];
    const float* W_self     = (const float*)d_in[3];
    const float* b_self     = (const float*)d_in[4];
    const float* W1         = (const float*)d_in[5];
    const float* b1         = (const float*)d_in[6];
    const float* gamma      = (const float*)d_in[7];
    const float* beta       = (const float*)d_in[8];
    const float* W2         = (const float*)d_in[9];
    const float* b2         = (const float*)d_in[10];
    float* out = (float*)d_out;

    cudaFuncSetAttribute(k_gemm1, cudaFuncAttributeMaxDynamicSharedMemorySize, SM_TOTAL);
    cudaFuncSetAttribute(k_gemm2, cudaFuncAttributeMaxDynamicSharedMemorySize, SM_TOTAL);

    k_init<<<(NREL * NN * (FDIM / 4) + 255) / 256, 256>>>(x);
    k_zero_stats<<<1, 512>>>();
    k_prepw<<<9, 256>>>(W1, W2, W_self);
    k_scatter<<<(NE * 32 + 255) / 256, 256>>>(x, edge_index, edge_type);
    dim3 g1(NBLK, NREL);
    k_gemm1<<<g1, NT, SM_TOTAL>>>(b1);
    k_bn<<<1, 512>>>(gamma, beta, b_self, b2);
    k_gemm2<<<NBLK, NT, SM_TOTAL>>>(x, out);
}

// round 9
// speedup vs baseline: 1.7020x; 1.1689x over previous
#include <cuda_runtime.h>
#include <cuda_bf16.h>
#include <cstdint>

#define NN 50000
#define NE 800000
#define FDIM 128
#define NREL 4
#define BN_EPS 1e-5f
#define TM 128
#define NBLK ((NN + TM - 1) / TM)   // 391
#define NT 256
#define NSEG (NREL * NN)            // 200000
#define CAP 32
#define MAXOVF 65536

// bf16 tile stride: 136 elems (272B)
#define STRD 136
#define TILE_B (TM * STRD * 2)      // 34816 B per bf16 tile
#define SM_AH 0
#define SM_AL TILE_B
#define SM_BH (2 * TILE_B)
#define SM_TOTAL (3 * TILE_B)       // 104448 B -> 2 blocks/SM
#define EPI_LD 132

// scratch
__device__ float4 g_h0[(size_t)NSEG * FDIM / 4];
__device__ float4 g_h1[(size_t)NSEG * FDIM / 4];
__device__ float  g_sum[NREL * FDIM];
__device__ float  g_sumsq[NREL * FDIM];
__device__ float4 g_scale[NREL * FDIM / 4];
__device__ float4 g_shift[NREL * FDIM / 4];
__device__ float4 g_bias[FDIM / 4];
__device__ uint4  g_wst[9][2][2048];
// gather structures
__device__ int    g_cnt[NSEG];
__device__ int    g_bkt[(size_t)NSEG * CAP];
__device__ int    g_ovf_cnt;
__device__ int2   g_ovf[MAXOVF];

// ---------------------------------------------------------------------------
__device__ __forceinline__ unsigned smem_u32(const void* p) {
    unsigned a;
    asm("{ .reg .u64 t; cvta.to.shared.u64 t, %1; cvt.u32.u64 %0, t; }"
        : "=r"(a) : "l"(p));
    return a;
}
__device__ __forceinline__ void cpa16(unsigned dst, const void* src) {
    asm volatile("cp.async.cg.shared.global [%0], [%1], 16;"
                 :: "r"(dst), "l"(src) : "memory");
}
#define CPA_COMMIT() asm volatile("cp.async.commit_group;" ::: "memory")
#define CPA_WAIT0()  asm volatile("cp.async.wait_group 0;" ::: "memory")

__device__ __forceinline__ void mma16816(float* c, const unsigned* a,
                                         unsigned b0, unsigned b1) {
    asm volatile(
        "mma.sync.aligned.m16n8k16.row.col.f32.bf16.bf16.f32 "
        "{%0,%1,%2,%3}, {%4,%5,%6,%7}, {%8,%9}, {%0,%1,%2,%3};"
        : "+f"(c[0]), "+f"(c[1]), "+f"(c[2]), "+f"(c[3])
        : "r"(a[0]), "r"(a[1]), "r"(a[2]), "r"(a[3]), "r"(b0), "r"(b1));
}

__device__ __forceinline__ void split_store(char* smem, int row, int c0, float4 v) {
    unsigned off = (unsigned)(row * STRD + c0) * 2;
    __nv_bfloat16 h0 = __float2bfloat16_rn(v.x), h1 = __float2bfloat16_rn(v.y);
    __nv_bfloat16 h2 = __float2bfloat16_rn(v.z), h3 = __float2bfloat16_rn(v.w);
    __nv_bfloat16 g0 = __float2bfloat16_rn(v.x - __bfloat162float(h0));
    __nv_bfloat16 g1 = __float2bfloat16_rn(v.y - __bfloat162float(h1));
    __nv_bfloat16 g2 = __float2bfloat16_rn(v.z - __bfloat162float(h2));
    __nv_bfloat16 g3 = __float2bfloat16_rn(v.w - __bfloat162float(h3));
    uint2 uh, ul;
    uh.x = (unsigned)__bfloat16_as_ushort(h0) | ((unsigned)__bfloat16_as_ushort(h1) << 16);
    uh.y = (unsigned)__bfloat16_as_ushort(h2) | ((unsigned)__bfloat16_as_ushort(h3) << 16);
    ul.x = (unsigned)__bfloat16_as_ushort(g0) | ((unsigned)__bfloat16_as_ushort(g1) << 16);
    ul.y = (unsigned)__bfloat16_as_ushort(g2) | ((unsigned)__bfloat16_as_ushort(g3) << 16);
    *(uint2*)(smem + SM_AH + off) = uh;
    *(uint2*)(smem + SM_AL + off) = ul;
}

__device__ __forceinline__ void mma_pass(const char* Asrc, const char* Bsrc,
                                         float acc[2][8][4],
                                         int wm, int wn, int g, int tg) {
#pragma unroll 1
    for (int ks = 0; ks < 8; ks++) {
        const int k0 = ks * 16;
        unsigned a[2][4];
#pragma unroll
        for (int mf = 0; mf < 2; mf++) {
            const char* ab = Asrc +
                (unsigned)((wm * 32 + mf * 16 + g) * STRD + k0 + tg * 2) * 2;
            a[mf][0] = *(const unsigned*)ab;
            a[mf][1] = *(const unsigned*)(ab + 8 * STRD * 2);
            a[mf][2] = *(const unsigned*)(ab + 16);
            a[mf][3] = *(const unsigned*)(ab + 8 * STRD * 2 + 16);
        }
#pragma unroll
        for (int nf = 0; nf < 8; nf++) {
            const char* bb = Bsrc +
                (unsigned)((wn * 64 + nf * 8 + g) * STRD + k0 + tg * 2) * 2;
            unsigned b0 = *(const unsigned*)bb;
            unsigned b1 = *(const unsigned*)(bb + 16);
            mma16816(acc[0][nf], a[0], b0, b1);
            mma16816(acc[1][nf], a[1], b0, b1);
        }
    }
}

__device__ __forceinline__ void copy_b(unsigned sb_dst, const uint4* src, int tid) {
#pragma unroll
    for (int i = 0; i < 8; i++) {
        int idx = i * NT + tid;
        int n = idx >> 4, c = idx & 15;
        cpa16(sb_dst + n * STRD * 2 + c * 16, src + idx);
    }
}

__device__ __forceinline__ void epi_store(float* E, float acc[2][8][4],
                                          int wm, int wn, int g, int tg) {
#pragma unroll
    for (int mf = 0; mf < 2; mf++)
#pragma unroll
        for (int nf = 0; nf < 8; nf++) {
            int row = wm * 32 + mf * 16 + g;
            int col = wn * 64 + nf * 8 + tg * 2;
            *(float2*)(E + row * EPI_LD + col) =
                make_float2(acc[mf][nf][0], acc[mf][nf][1]);
            *(float2*)(E + (row + 8) * EPI_LD + col) =
                make_float2(acc[mf][nf][2], acc[mf][nf][3]);
        }
}

// ---------------------------------------------------------------------------
// gather pipeline: zero counters -> bucket edges -> gather (+ self term)
// ---------------------------------------------------------------------------
__global__ void k_zero_cnt() {
    int i = blockIdx.x * blockDim.x + threadIdx.x;
    if (i < NSEG) g_cnt[i] = 0;
    if (i < NREL * FDIM) { g_sum[i] = 0.f; g_sumsq[i] = 0.f; }
    if (i == 0) g_ovf_cnt = 0;
}

__global__ void k_bucket(const int* __restrict__ edge_index,
                         const int* __restrict__ edge_type) {
    int e = blockIdx.x * blockDim.x + threadIdx.x;
    if (e >= NE) return;
    int src = edge_index[e];
    int dst = edge_index[NE + e];
    int rel = edge_type[e];
    if ((unsigned)src >= NN || (unsigned)dst >= NN || (unsigned)rel >= NREL) return;
    int s = rel * NN + dst;
    int p = atomicAdd(&g_cnt[s], 1);
    if (p < CAP) {
        g_bkt[(size_t)s * CAP + p] = src;
    } else {
        int o = atomicAdd(&g_ovf_cnt, 1);
        if (o < MAXOVF) g_ovf[o] = make_int2(s, src);
    }
}

// one warp per segment: h0[s] = x[s % NN] + sum_i x[bkt[s][i]]
__global__ void __launch_bounds__(256) k_gather(const float* __restrict__ x) {
    int w = (blockIdx.x * blockDim.x + threadIdx.x) >> 5;
    if (w >= NSEG) return;
    const int q = threadIdx.x & 31;
    const float4* x4 = (const float4*)x;

    int n = g_cnt[w];
    if (n > CAP) n = CAP;
    int myidx = g_bkt[(size_t)w * CAP + q];   // coalesced; lanes >= n unused
    int node = w % NN;

    float4 acc = x4[(size_t)node * 32 + q];
#pragma unroll 4
    for (int i = 0; i < n; i++) {
        int s = __shfl_sync(0xFFFFFFFFu, myidx, i);
        float4 v = x4[(size_t)s * 32 + q];
        acc.x += v.x; acc.y += v.y; acc.z += v.z; acc.w += v.w;
    }
    g_h0[(size_t)w * 32 + q] = acc;
}

// rare overflow edges: warp-per-entry RED into h0 (runs after k_gather)
__global__ void k_overflow(const float* __restrict__ x) {
    int total = g_ovf_cnt;
    if (total > MAXOVF) total = MAXOVF;
    const int q = threadIdx.x & 31;
    int w = (blockIdx.x * blockDim.x + threadIdx.x) >> 5;
    const int nw = (gridDim.x * blockDim.x) >> 5;
    for (; w < total; w += nw) {
        int2 ent = g_ovf[w];
        float4 v = ((const float4*)x)[(size_t)ent.y * 32 + q];
        float* p = (float*)g_h0 + (size_t)ent.x * FDIM + q * 4;
        asm volatile("red.global.add.v4.f32 [%0], {%1, %2, %3, %4};"
                     :: "l"(__cvta_generic_to_global(p)),
                        "f"(v.x), "f"(v.y), "f"(v.z), "f"(v.w)
                     : "memory");
    }
}

// ---------------------------------------------------------------------------
__global__ void k_prepw(const float* __restrict__ W1,
                        const float* __restrict__ W2,
                        const float* __restrict__ W_self) {
    int t = blockIdx.x;   // 0..8
    const float* src = (t < 4) ? W1 + t * FDIM * FDIM
                     : (t < 8) ? W2 + (t - 4) * FDIM * FDIM
                               : W_self;
    unsigned short* dh = (unsigned short*)g_wst[t][0];
    unsigned short* dl = (unsigned short*)g_wst[t][1];
    for (int idx = threadIdx.x; idx < FDIM * FDIM; idx += blockDim.x) {
        int k = idx >> 7;
        int n = idx & 127;
        float w = src[idx];
        __nv_bfloat16 hi = __float2bfloat16_rn(w);
        __nv_bfloat16 lo = __float2bfloat16_rn(w - __bfloat162float(hi));
        dh[n * FDIM + k] = __bfloat16_as_ushort(hi);
        dl[n * FDIM + k] = __bfloat16_as_ushort(lo);
    }
}

__global__ void k_bn(const float* __restrict__ gamma, const float* __restrict__ beta,
                     const float* __restrict__ b_self, const float* __restrict__ b2) {
    int i = threadIdx.x;
    if (i < NREL * FDIM) {
        const float invN = 1.f / (float)NN;
        float mean = g_sum[i] * invN;
        float var = g_sumsq[i] * invN - mean * mean;
        float sc = gamma[i] * rsqrtf(var + BN_EPS);
        ((float*)g_scale)[i] = sc;
        ((float*)g_shift)[i] = beta[i] - mean * sc;
    }
    if (i < FDIM) {
        float b = b_self[i];
#pragma unroll
        for (int r = 0; r < NREL; r++) b += b2[r * FDIM + i];
        ((float*)g_bias)[i] = b;
    }
}

// ---------------------------------------------------------------------------
// GEMM1 (mma.sync bf16-split, 3-buffer): h1[r] = h0[r] @ W1[r] + b1[r]
// ---------------------------------------------------------------------------
__global__ void __launch_bounds__(NT, 2) k_gemm1(const float* __restrict__ b1) {
    extern __shared__ char smem[];
    const unsigned sb = smem_u32(smem);
    const int tid = threadIdx.x;
    const int wid = tid >> 5, lid = tid & 31;
    const int wm = wid & 3, wn = wid >> 2;
    const int g = lid >> 2, tg = lid & 3;
    const int r = blockIdx.y;
    const int n0 = blockIdx.x * TM;
    const int valid = min(NN - n0, TM);

    copy_b(sb + SM_BH, g_wst[r][0], tid);
    CPA_COMMIT();

    const float* A = (const float*)g_h0 + (size_t)r * NN * FDIM;
#pragma unroll
    for (int i = 0; i < 16; i++) {
        int idx = i * NT + tid;
        int row = idx >> 5, c4 = idx & 31;
        float4 v = make_float4(0.f, 0.f, 0.f, 0.f);
        if (row < valid) v = ((const float4*)(A + (size_t)(n0 + row) * FDIM))[c4];
        split_store(smem, row, c4 * 4, v);
    }
    CPA_WAIT0();
    __syncthreads();

    float acc[2][8][4];
#pragma unroll
    for (int mf = 0; mf < 2; mf++)
#pragma unroll
        for (int nf = 0; nf < 8; nf++)
#pragma unroll
            for (int j = 0; j < 4; j++) acc[mf][nf][j] = 0.f;

    mma_pass(smem + SM_AH, smem + SM_BH, acc, wm, wn, g, tg);
    mma_pass(smem + SM_AL, smem + SM_BH, acc, wm, wn, g, tg);
    __syncthreads();
    copy_b(sb + SM_AL, g_wst[r][1], tid);
    CPA_COMMIT();
    CPA_WAIT0();
    __syncthreads();
    mma_pass(smem + SM_AH, smem + SM_AL, acc, wm, wn, g, tg);
    __syncthreads();

    float* E = (float*)smem;
    epi_store(E, acc, wm, wn, g, tg);
    __syncthreads();

    const int c4 = tid & 31, rg = tid >> 5;
    float4 bias = *(const float4*)(b1 + r * FDIM + c4 * 4);
    float s4[4] = {0, 0, 0, 0}, q4[4] = {0, 0, 0, 0};
    float* Hout = (float*)g_h1 + (size_t)r * NN * FDIM;
#pragma unroll
    for (int i = 0; i < 16; i++) {
        int row = i * 8 + rg;
        if (row < valid) {
            float4 v = *(float4*)(E + row * EPI_LD + c4 * 4);
            v.x += bias.x; v.y += bias.y; v.z += bias.z; v.w += bias.w;
            s4[0] += v.x; q4[0] += v.x * v.x;
            s4[1] += v.y; q4[1] += v.y * v.y;
            s4[2] += v.z; q4[2] += v.z * v.z;
            s4[3] += v.w; q4[3] += v.w * v.w;
            *(float4*)(Hout + (size_t)(n0 + row) * FDIM + c4 * 4) = v;
        }
    }
    float* redS = (float*)(smem + SM_BH);
    float* redQ = redS + 8 * FDIM;
#pragma unroll
    for (int j = 0; j < 4; j++) {
        redS[rg * FDIM + c4 * 4 + j] = s4[j];
        redQ[rg * FDIM + c4 * 4 + j] = q4[j];
    }
    __syncthreads();
    if (tid < FDIM) {
        float S = 0.f, Q = 0.f;
#pragma unroll
        for (int p = 0; p < 8; p++) { S += redS[p * FDIM + tid]; Q += redQ[p * FDIM + tid]; }
        atomicAdd(&g_sum[r * FDIM + tid], S);
        atomicAdd(&g_sumsq[r * FDIM + tid], Q);
    }
}

// ---------------------------------------------------------------------------
// GEMM2 (mma.sync, K=640, 3-buffer)
// ---------------------------------------------------------------------------
__global__ void __launch_bounds__(NT, 2) k_gemm2(const float* __restrict__ x,
                                                 float* __restrict__ out) {
    extern __shared__ char smem[];
    const unsigned sb = smem_u32(smem);
    const int tid = threadIdx.x;
    const int wid = tid >> 5, lid = tid & 31;
    const int wm = wid & 3, wn = wid >> 2;
    const int g = lid >> 2, tg = lid & 3;
    const int n0 = blockIdx.x * TM;
    const int valid = min(NN - n0, TM);

    float acc[2][8][4];
#pragma unroll
    for (int mf = 0; mf < 2; mf++)
#pragma unroll
        for (int nf = 0; nf < 8; nf++)
#pragma unroll
            for (int j = 0; j < 4; j++) acc[mf][nf][j] = 0.f;

    for (int r = 0; r < NREL + 1; r++) {
        __syncthreads();
        const int t = (r < NREL) ? 4 + r : 8;

        copy_b(sb + SM_BH, g_wst[t][0], tid);
        CPA_COMMIT();

        if (r < NREL) {
            const float* H = (const float*)g_h1 + (size_t)r * NN * FDIM;
#pragma unroll
            for (int i = 0; i < 16; i++) {
                int idx = i * NT + tid;
                int row = idx >> 5, c4 = idx & 31;
                float4 v = make_float4(0.f, 0.f, 0.f, 0.f);
                if (row < valid) {
                    v = ((const float4*)(H + (size_t)(n0 + row) * FDIM))[c4];
                    float4 sc = g_scale[r * (FDIM / 4) + c4];
                    float4 sh = g_shift[r * (FDIM / 4) + c4];
                    v.x = fmaxf(v.x * sc.x + sh.x, 0.f);
                    v.y = fmaxf(v.y * sc.y + sh.y, 0.f);
                    v.z = fmaxf(v.z * sc.z + sh.z, 0.f);
                    v.w = fmaxf(v.w * sc.w + sh.w, 0.f);
                }
                split_store(smem, row, c4 * 4, v);
            }
        } else {
#pragma unroll
            for (int i = 0; i < 16; i++) {
                int idx = i * NT + tid;
                int row = idx >> 5, c4 = idx & 31;
                float4 v = make_float4(0.f, 0.f, 0.f, 0.f);
                if (row < valid) v = ((const float4*)(x + (size_t)(n0 + row) * FDIM))[c4];
                split_store(smem, row, c4 * 4, v);
            }
        }
        CPA_WAIT0();
        __syncthreads();

        mma_pass(smem + SM_AH, smem + SM_BH, acc, wm, wn, g, tg);
        mma_pass(smem + SM_AL, smem + SM_BH, acc, wm, wn, g, tg);
        __syncthreads();
        copy_b(sb + SM_AL, g_wst[t][1], tid);
        CPA_COMMIT();
        CPA_WAIT0();
        __syncthreads();
        mma_pass(smem + SM_AH, smem + SM_AL, acc, wm, wn, g, tg);
    }
    __syncthreads();

    float* E = (float*)smem;
    epi_store(E, acc, wm, wn, g, tg);
    __syncthreads();

    const int c4 = tid & 31, rg = tid >> 5;
    float4 bias = g_bias[c4];
#pragma unroll
    for (int i = 0; i < 16; i++) {
        int row = i * 8 + rg;
        if (row < valid) {
            float4 v = *(float4*)(E + row * EPI_LD + c4 * 4);
            v.x += bias.x; v.y += bias.y; v.z += bias.z; v.w += bias.w;
            *(float4*)(out + (size_t)(n0 + row) * FDIM + c4 * 4) = v;
        }
    }
}

extern "C" void kernel_launch(void* const* d_in, const int* in_sizes, int n_in,
                              void* d_out, int out_size) {
    const float* x          = (const float*)d_in[0];
    const int*   edge_index = (const int*)d_in[1];   // int32 (JAX x64 disabled)
    const int*   edge_type  = (const int*)d_in[2];
    const float* W_self     = (const float*)d_in[3];
    const float* b_self     = (const float*)d_in[4];
    const float* W1         = (const float*)d_in[5];
    const float* b1         = (const float*)d_in[6];
    const float* gamma      = (const float*)d_in[7];
    const float* beta       = (const float*)d_in[8];
    const float* W2         = (const float*)d_in[9];
    const float* b2         = (const float*)d_in[10];
    float* out = (float*)d_out;

    cudaFuncSetAttribute(k_gemm1, cudaFuncAttributeMaxDynamicSharedMemorySize, SM_TOTAL);
    cudaFuncSetAttribute(k_gemm2, cudaFuncAttributeMaxDynamicSharedMemorySize, SM_TOTAL);

    k_zero_cnt<<<(NSEG + 255) / 256, 256>>>();
    k_prepw<<<9, 256>>>(W1, W2, W_self);
    k_bucket<<<(NE + 255) / 256, 256>>>(edge_index, edge_type);
    k_gather<<<(NSEG * 32 + 255) / 256, 256>>>(x);
    k_overflow<<<64, 256>>>(x);
    dim3 g1(NBLK, NREL);
    k_gemm1<<<g1, NT, SM_TOTAL>>>(b1);
    k_bn<<<1, 512>>>(gamma, beta, b_self, b2);
    k_gemm2<<<NBLK, NT, SM_TOTAL>>>(x, out);
}